// round 1
// baseline (speedup 1.0000x reference)
#include <cuda_runtime.h>
#include <math.h>

#define BB 4
#define CC 8
#define HH 256
#define WW 256
#define INF_D 512

// Static device scratch (no allocations allowed)
__device__ unsigned short g_gin[BB*CC*HH*WW];   // 4 MB: per-class row distance (inside transform)
__device__ unsigned short g_r[BB*HH*WW];        // 0.5 MB: row distance to nearest different class
__device__ float          g_d[BB*CC*HH*WW];     // 8 MB: signed distance maps
__device__ int            g_cnt[BB*CC];         // class presence counts
__device__ float          g_part[1024];         // block partial sums

// ---------------------------------------------------------------------------
__global__ void k_init() {
    int i = threadIdx.x;
    if (i < BB*CC) g_cnt[i] = 0;
}

// Row pass: one block per (b, h) row. Computes g_gin for all 8 classes,
// g_r, and per-class pixel counts.
__global__ void k_rowpass(const int* __restrict__ target) {
    const int row = blockIdx.x;          // b*HH + h
    const int b   = row / HH;
    const int h   = row % HH;
    const int j   = threadIdx.x;

    __shared__ int s[WW];
    __shared__ int scnt[CC];
    if (j < CC) scnt[j] = 0;
    const int t = target[row * WW + j];
    s[j] = t;
    __syncthreads();
    atomicAdd(&scnt[t], 1);

    // r: nearest column with a different class (outward scan, early exit)
    int r = INF_D;
    for (int dd = 1; dd < WW; ++dd) {
        const int lo = j - dd, hi = j + dd;
        if ((lo >= 0 && s[lo] != t) || (hi < WW && s[hi] != t)) { r = dd; break; }
    }
    g_r[row * WW + j] = (unsigned short)r;

    // gin[c]: nearest column with class c
    #pragma unroll
    for (int c = 0; c < CC; ++c) {
        int g;
        if (t == c) {
            g = 0;
        } else {
            g = INF_D;
            for (int dd = 1; dd < WW; ++dd) {
                const int lo = j - dd, hi = j + dd;
                if ((lo >= 0 && s[lo] == c) || (hi < WW && s[hi] == c)) { g = dd; break; }
            }
        }
        g_gin[((b*CC + c)*HH + h)*WW + j] = (unsigned short)g;
    }

    __syncthreads();
    if (j < CC) atomicAdd(&g_cnt[b*CC + j], scnt[j]);
}

// Column pass: one block per (b, c, j) column; thread i = output row.
// dt2_in[i] = min_k (i-k)^2 + gin^2[k], dt2_out[i] = min_k (i-k)^2 + gout^2[k]
__global__ void k_colpass(const int* __restrict__ target) {
    const int idx = blockIdx.x;          // bc*WW + j
    const int j   = idx % WW;
    const int bc  = idx / WW;
    const int b   = bc / CC;
    const int c   = bc % CC;
    const int i   = threadIdx.x;

    __shared__ float2 g2[HH];            // x = gin^2, y = gout^2
    {
        const int   t    = target[(b*HH + i)*WW + j];
        const float gin  = (float)g_gin[(bc*HH + i)*WW + j];
        const float gout = (t == c) ? (float)g_r[(b*HH + i)*WW + j] : 0.0f;
        g2[i] = make_float2(gin * gin, gout * gout);
    }
    __syncthreads();

    float din2  = 3.0e8f;
    float dout2 = 3.0e8f;
    const float fi = (float)i;
    #pragma unroll 8
    for (int k = 0; k < HH; ++k) {
        const float  dk = fi - (float)k;
        const float2 g  = g2[k];
        din2  = fminf(din2,  fmaf(dk, dk, g.x));
        dout2 = fminf(dout2, fmaf(dk, dk, g.y));
    }
    g_d[(bc*HH + i)*WW + j] = sqrtf(din2) - sqrtf(dout2);
}

// Reduce: one thread per pixel (b,h,w). Fused softmax over 8 channels,
// accumulate p_c * d_c * present_c, deterministic block tree reduce.
__global__ void k_reduce(const float* __restrict__ output) {
    const int p  = blockIdx.x * blockDim.x + threadIdx.x;  // 0 .. B*H*W-1
    const int b  = p / (HH*WW);
    const int hw = p % (HH*WW);

    float lg[CC];
    float m = -1e30f;
    #pragma unroll
    for (int c = 0; c < CC; ++c) {
        lg[c] = output[(b*CC + c)*(HH*WW) + hw];
        m = fmaxf(m, lg[c]);
    }
    float sum = 0.0f;
    #pragma unroll
    for (int c = 0; c < CC; ++c) { lg[c] = __expf(lg[c] - m); sum += lg[c]; }
    const float inv = 1.0f / sum;

    float acc = 0.0f;
    #pragma unroll
    for (int c = 0; c < CC; ++c) {
        const float present = (g_cnt[b*CC + c] > 0) ? 1.0f : 0.0f;
        acc += lg[c] * inv * g_d[(b*CC + c)*(HH*WW) + hw] * present;
    }

    __shared__ float sred[256];
    sred[threadIdx.x] = acc;
    __syncthreads();
    #pragma unroll
    for (int s = 128; s > 0; s >>= 1) {
        if (threadIdx.x < s) sred[threadIdx.x] += sred[threadIdx.x + s];
        __syncthreads();
    }
    if (threadIdx.x == 0) g_part[blockIdx.x] = sred[0];
}

__global__ void k_final(float* __restrict__ out) {
    __shared__ float sred[1024];
    const int i = threadIdx.x;
    sred[i] = g_part[i];
    __syncthreads();
    #pragma unroll
    for (int s = 512; s > 0; s >>= 1) {
        if (i < s) sred[i] += sred[i + s];
        __syncthreads();
    }
    if (i == 0) {
        int n = 0;
        #pragma unroll
        for (int k = 0; k < BB*CC; ++k) n += (g_cnt[k] > 0) ? 1 : 0;
        const float nf = (n > 0) ? (float)n : 1.0f;
        out[0] = sred[0] / nf;
    }
}

// ---------------------------------------------------------------------------
extern "C" void kernel_launch(void* const* d_in, const int* in_sizes, int n_in,
                              void* d_out, int out_size) {
    const float* output = (const float*)d_in[0];   // [4,8,256,256] fp32
    const int*   target = (const int*)d_in[1];     // [4,256,256] int32
    float*       out    = (float*)d_out;           // scalar

    k_init   <<<1, 32>>>();
    k_rowpass<<<BB*HH, WW>>>(target);
    k_colpass<<<BB*CC*WW, HH>>>(target);
    k_reduce <<<(BB*HH*WW)/256, 256>>>(output);
    k_final  <<<1, 1024>>>(out);
}

// round 2
// speedup vs baseline: 2.2049x; 2.2049x over previous
#include <cuda_runtime.h>
#include <math.h>

#define BB 4
#define CC 8
#define HH 256
#define WW 256
#define INF_D 512

// Static device scratch (no allocations allowed)
__device__ unsigned short g_gin[BB*CC*HH*WW];   // 4 MB: per-class row distance (inside)
__device__ unsigned short g_tr[BB*HH*WW];       // 0.5 MB: packed (t<<10 | r)
__device__ float4         g_d4[BB*CC*HH*WW/4];  // 8 MB: signed distance maps (16B aligned)
__device__ int            g_cnt[BB*CC];         // class presence counts
__device__ float          g_part[256];          // block partial sums

// ---------------------------------------------------------------------------
__global__ void k_init() {
    int i = threadIdx.x;
    if (i < BB*CC) g_cnt[i] = 0;
}

// Row pass: one block per (b, h) row. Computes g_gin for all 8 classes,
// packed (t, r), and per-class pixel counts.
__global__ void k_rowpass(const int* __restrict__ target) {
    const int row = blockIdx.x;          // b*HH + h
    const int b   = row / HH;
    const int h   = row % HH;
    const int j   = threadIdx.x;

    __shared__ int s[WW];
    __shared__ int scnt[CC];
    if (j < CC) scnt[j] = 0;
    const int t = target[row * WW + j];
    s[j] = t;
    __syncthreads();
    atomicAdd(&scnt[t], 1);

    // r: nearest column with a different class (outward scan, early exit)
    int r = INF_D;
    for (int dd = 1; dd < WW; ++dd) {
        const int lo = j - dd, hi = j + dd;
        if ((lo >= 0 && s[lo] != t) || (hi < WW && s[hi] != t)) { r = dd; break; }
    }
    g_tr[row * WW + j] = (unsigned short)(r | (t << 10));

    // gin[c]: nearest column with class c
    #pragma unroll
    for (int c = 0; c < CC; ++c) {
        int g;
        if (t == c) {
            g = 0;
        } else {
            g = INF_D;
            for (int dd = 1; dd < WW; ++dd) {
                const int lo = j - dd, hi = j + dd;
                if ((lo >= 0 && s[lo] == c) || (hi < WW && s[hi] == c)) { g = dd; break; }
            }
        }
        g_gin[((b*CC + c)*HH + h)*WW + j] = (unsigned short)g;
    }

    __syncthreads();
    if (j < CC) atomicAdd(&g_cnt[b*CC + j], scnt[j]);
}

// Column pass: one block per (b, c, j) column; thread i = output row.
// Exact EDT combine via outward scan with early exit:
//   dt2[i] starts at g2[i] (k=i); after examining d, any unexamined k has
//   (i-k)^2 >= d^2, so exit when d^2 >= dt2 is exact.
__global__ void k_colpass() {
    const int idx = blockIdx.x;          // bc*WW + j
    const int j   = idx % WW;
    const int bc  = idx / WW;
    const int b   = bc / CC;
    const int c   = bc % CC;
    const int i   = threadIdx.x;

    __shared__ float s_in[HH];
    __shared__ float s_out[HH];
    {
        const unsigned v = g_tr[(b*HH + i)*WW + j];
        const int t = (int)(v >> 10);
        const float gout = (t == c) ? (float)(v & 1023u) : 0.0f;
        const float gin  = (float)g_gin[(bc*HH + i)*WW + j];
        s_in[i]  = gin * gin;
        s_out[i] = gout * gout;
    }
    __syncthreads();

    float din2  = s_in[i];
    float dout2 = s_out[i];
    for (int d = 1; d < HH; ++d) {
        const float dd2 = (float)(d * d);
        if (dd2 >= din2 && dd2 >= dout2) break;
        const int lo = i - d, hi = i + d;
        if (lo >= 0) {
            din2  = fminf(din2,  dd2 + s_in[lo]);
            dout2 = fminf(dout2, dd2 + s_out[lo]);
        }
        if (hi < HH) {
            din2  = fminf(din2,  dd2 + s_in[hi]);
            dout2 = fminf(dout2, dd2 + s_out[hi]);
        }
    }
    ((float*)g_d4)[(bc*HH + i)*WW + j] = sqrtf(din2) - sqrtf(dout2);
}

// Reduce: each thread handles 4 consecutive pixels (float4). Fused softmax
// over 8 channels, accumulate p_c * d_c * present_c, deterministic tree sum.
__global__ void k_reduce(const float* __restrict__ output) {
    const int q   = blockIdx.x * 256 + threadIdx.x;   // 0 .. 65535 (pixel/4)
    const int b   = q >> 14;                          // / (HH*WW/4)
    const int hw4 = q & 16383;
    const float4* out4 = (const float4*)output;

    float4 lg[CC];
    float mx = -1e30f, my = -1e30f, mz = -1e30f, mw = -1e30f;
    #pragma unroll
    for (int c = 0; c < CC; ++c) {
        lg[c] = out4[(b*CC + c)*16384 + hw4];
        mx = fmaxf(mx, lg[c].x); my = fmaxf(my, lg[c].y);
        mz = fmaxf(mz, lg[c].z); mw = fmaxf(mw, lg[c].w);
    }
    float sx = 0.f, sy = 0.f, sz = 0.f, sw = 0.f;
    #pragma unroll
    for (int c = 0; c < CC; ++c) {
        lg[c].x = __expf(lg[c].x - mx); sx += lg[c].x;
        lg[c].y = __expf(lg[c].y - my); sy += lg[c].y;
        lg[c].z = __expf(lg[c].z - mz); sz += lg[c].z;
        lg[c].w = __expf(lg[c].w - mw); sw += lg[c].w;
    }
    const float ix = 1.f/sx, iy = 1.f/sy, iz = 1.f/sz, iw = 1.f/sw;

    float acc = 0.f;
    #pragma unroll
    for (int c = 0; c < CC; ++c) {
        const float pres = (g_cnt[b*CC + c] > 0) ? 1.0f : 0.0f;
        const float4 dd = g_d4[(b*CC + c)*16384 + hw4];
        acc += pres * (lg[c].x*ix*dd.x + lg[c].y*iy*dd.y +
                       lg[c].z*iz*dd.z + lg[c].w*iw*dd.w);
    }

    __shared__ float sred[256];
    sred[threadIdx.x] = acc;
    __syncthreads();
    #pragma unroll
    for (int s = 128; s > 0; s >>= 1) {
        if (threadIdx.x < s) sred[threadIdx.x] += sred[threadIdx.x + s];
        __syncthreads();
    }
    if (threadIdx.x == 0) g_part[blockIdx.x] = sred[0];
}

__global__ void k_final(float* __restrict__ out) {
    __shared__ float sred[256];
    const int i = threadIdx.x;
    sred[i] = g_part[i];
    __syncthreads();
    #pragma unroll
    for (int s = 128; s > 0; s >>= 1) {
        if (i < s) sred[i] += sred[i + s];
        __syncthreads();
    }
    if (i == 0) {
        int n = 0;
        #pragma unroll
        for (int k = 0; k < BB*CC; ++k) n += (g_cnt[k] > 0) ? 1 : 0;
        const float nf = (n > 0) ? (float)n : 1.0f;
        out[0] = sred[0] / nf;
    }
}

// ---------------------------------------------------------------------------
extern "C" void kernel_launch(void* const* d_in, const int* in_sizes, int n_in,
                              void* d_out, int out_size) {
    const float* output = (const float*)d_in[0];   // [4,8,256,256] fp32
    const int*   target = (const int*)d_in[1];     // [4,256,256] int32
    float*       out    = (float*)d_out;           // scalar

    k_init   <<<1, 32>>>();
    k_rowpass<<<BB*HH, WW>>>(target);
    k_colpass<<<BB*CC*WW, HH>>>();
    k_reduce <<<(BB*HH*WW)/(4*256), 256>>>(output);
    k_final  <<<1, 256>>>(out);
}

// round 5
// speedup vs baseline: 5.0020x; 2.2686x over previous
#include <cuda_runtime.h>
#include <math.h>

#define BB 4
#define CC 8
#define HH 256
#define WW 256
#define INF_D 512
#define JT 16                         // columns per colpass tile

// Static device scratch (no allocations allowed)
__device__ unsigned short g_gin[BB*CC*HH*WW];   // 4 MB: per-class row distance (inside)
__device__ unsigned short g_tr[BB*HH*WW];       // 0.5 MB: packed (t<<10 | r)
__device__ float4         g_d4[BB*CC*HH*WW/4];  // 8 MB: signed distance maps
__device__ int            g_cnt[BB*CC];         // class presence counts
__device__ float          g_part[512];          // block partial sums

// ---------------------------------------------------------------------------
__global__ void k_init() {
    int i = threadIdx.x;
    if (i < BB*CC) g_cnt[i] = 0;
}

// Nearest set bit distance in a 256-bit mask (8 words), bits optionally
// inverted by xor with `inv`. Returns 0 if bit j itself is set; INF_D if none.
__device__ __forceinline__ int nearest_bit(const unsigned* wd, unsigned inv, int j) {
    const int wj = j >> 5, bj = j & 31;
    const unsigned cur = wd[wj] ^ inv;
    int dl = INF_D, dr = INF_D;

    unsigned m = cur & (0xffffffffu >> (31 - bj));   // bits [0..bj]
    if (m) {
        dl = bj - (31 - __clz(m));
    } else {
        #pragma unroll
        for (int w = 6; w >= 0; --w) {               // first nonzero word below
            if (w < wj) {
                const unsigned mw = wd[w] ^ inv;
                if (mw) { dl = j - (w*32 + 31 - __clz(mw)); break; }
            }
        }
    }
    m = cur >> bj;                                   // bits [bj..31]
    if (m) {
        dr = __ffs(m) - 1;
    } else {
        #pragma unroll
        for (int w = 1; w <= 7; ++w) {               // first nonzero word above
            if (w > wj) {
                const unsigned mw = wd[w] ^ inv;
                if (mw) { dr = (w*32 + __ffs(mw) - 1) - j; break; }
            }
        }
    }
    int d = dl < dr ? dl : dr;
    return d < INF_D ? d : INF_D;
}

// Row pass: one block per (b, h) row. Bitmask-based nearest-site distances.
__global__ void k_rowpass(const int* __restrict__ target) {
    const int row = blockIdx.x;          // b*HH + h
    const int b   = row / HH;
    const int h   = row % HH;
    const int j   = threadIdx.x;
    const int w   = j >> 5;              // warp id 0..7
    const int ln  = j & 31;

    __shared__ unsigned mask[CC][8];     // 256-bit occupancy per class
    const int t = target[row * WW + j];

    #pragma unroll
    for (int c = 0; c < CC; ++c) {
        const unsigned m = __ballot_sync(0xffffffffu, t == c);
        if (ln == 0) mask[c][w] = m;
    }
    __syncthreads();

    // r: nearest column whose class differs from t  (complement of mask[t])
    const int r = nearest_bit(mask[t], 0xffffffffu, j);
    g_tr[row * WW + j] = (unsigned short)(r | (t << 10));

    // gin[c]: nearest column with class c
    #pragma unroll
    for (int c = 0; c < CC; ++c) {
        const int g = nearest_bit(mask[c], 0u, j);
        g_gin[((b*CC + c)*HH + h)*WW + j] = (unsigned short)g;
    }

    // presence counts: threads 0..7, one class each
    if (j < CC) {
        int cnt = 0;
        #pragma unroll
        for (int k = 0; k < 8; ++k) cnt += __popc(mask[j][k]);
        if (cnt) atomicAdd(&g_cnt[b*CC + j], cnt);
    }
}

// Column pass, tiled: one block per (bc, 16-column tile). Coalesced tile
// load into smem, then exact early-exit outward scan per output pixel.
__global__ void k_colpass() {
    const int jt  = blockIdx.x & (WW/JT - 1);   // 0..15
    const int bc  = blockIdx.x / (WW/JT);
    const int b   = bc >> 3;
    const int c   = bc & 7;
    const int j0  = jt * JT;

    __shared__ float s_in[HH][JT];
    __shared__ float s_out[HH][JT];

    const int jj = threadIdx.x & (JT - 1);
    const int k0 = threadIdx.x / JT;            // 0..15

    // Cooperative coalesced load: warp lanes span 2 rows x 16 contiguous cols.
    #pragma unroll
    for (int m = 0; m < HH/16; ++m) {
        const int k = k0 + 16*m;
        const unsigned v = g_tr[(b*HH + k)*WW + j0 + jj];
        const int t = (int)(v >> 10);
        const float gout = (t == c) ? (float)(v & 1023u) : 0.0f;
        const float gin  = (float)g_gin[(bc*HH + k)*WW + j0 + jj];
        s_in[k][jj]  = gin * gin;
        s_out[k][jj] = gout * gout;
    }
    __syncthreads();

    // Each thread: column jj, rows i = k0 + 16*m (16 outputs).
    // Exact early exit: after rejecting distance d, any unexamined k has
    // (i-k)^2 >= d^2, so stop when d^2 >= both running minima.
    for (int m = 0; m < HH/16; ++m) {
        const int i = k0 + 16*m;
        float din2  = s_in[i][jj];
        float dout2 = s_out[i][jj];
        for (int d = 1; d < HH; ++d) {
            const float dd2 = (float)(d * d);
            if (dd2 >= din2 && dd2 >= dout2) break;
            const int lo = i - d, hi = i + d;
            if (lo >= 0) {
                din2  = fminf(din2,  dd2 + s_in[lo][jj]);
                dout2 = fminf(dout2, dd2 + s_out[lo][jj]);
            }
            if (hi < HH) {
                din2  = fminf(din2,  dd2 + s_in[hi][jj]);
                dout2 = fminf(dout2, dd2 + s_out[hi][jj]);
            }
        }
        ((float*)g_d4)[(bc*HH + i)*WW + j0 + jj] = sqrtf(din2) - sqrtf(dout2);
    }
}

// Reduce: each thread handles 4 consecutive pixels (float4). 512 blocks x 128
// threads for latency hiding. Fused softmax over the 8 channels.
__global__ void k_reduce(const float* __restrict__ output) {
    const int q   = blockIdx.x * 128 + threadIdx.x;   // 0 .. 65535 (pixel/4)
    const int b   = q >> 14;
    const int hw4 = q & 16383;
    const float4* out4 = (const float4*)output;

    float4 lg[CC];
    float mx = -1e30f, my = -1e30f, mz = -1e30f, mw = -1e30f;
    #pragma unroll
    for (int c = 0; c < CC; ++c) {
        lg[c] = out4[(b*CC + c)*16384 + hw4];
        mx = fmaxf(mx, lg[c].x); my = fmaxf(my, lg[c].y);
        mz = fmaxf(mz, lg[c].z); mw = fmaxf(mw, lg[c].w);
    }
    float sx = 0.f, sy = 0.f, sz = 0.f, sw = 0.f;
    #pragma unroll
    for (int c = 0; c < CC; ++c) {
        lg[c].x = __expf(lg[c].x - mx); sx += lg[c].x;
        lg[c].y = __expf(lg[c].y - my); sy += lg[c].y;
        lg[c].z = __expf(lg[c].z - mz); sz += lg[c].z;
        lg[c].w = __expf(lg[c].w - mw); sw += lg[c].w;
    }
    const float ix = 1.f/sx, iy = 1.f/sy, iz = 1.f/sz, iw = 1.f/sw;

    float acc = 0.f;
    #pragma unroll
    for (int c = 0; c < CC; ++c) {
        const float pres = (g_cnt[b*CC + c] > 0) ? 1.0f : 0.0f;
        const float4 dd = g_d4[(b*CC + c)*16384 + hw4];
        acc += pres * (lg[c].x*ix*dd.x + lg[c].y*iy*dd.y +
                       lg[c].z*iz*dd.z + lg[c].w*iw*dd.w);
    }

    __shared__ float sred[128];
    sred[threadIdx.x] = acc;
    __syncthreads();
    #pragma unroll
    for (int s = 64; s > 0; s >>= 1) {
        if (threadIdx.x < s) sred[threadIdx.x] += sred[threadIdx.x + s];
        __syncthreads();
    }
    if (threadIdx.x == 0) g_part[blockIdx.x] = sred[0];
}

__global__ void k_final(float* __restrict__ out) {
    __shared__ float sred[512];
    const int i = threadIdx.x;
    sred[i] = g_part[i];
    __syncthreads();
    #pragma unroll
    for (int s = 256; s > 0; s >>= 1) {
        if (i < s) sred[i] += sred[i + s];
        __syncthreads();
    }
    if (i == 0) {
        int n = 0;
        #pragma unroll
        for (int k = 0; k < BB*CC; ++k) n += (g_cnt[k] > 0) ? 1 : 0;
        const float nf = (n > 0) ? (float)n : 1.0f;
        out[0] = sred[0] / nf;
    }
}

// ---------------------------------------------------------------------------
extern "C" void kernel_launch(void* const* d_in, const int* in_sizes, int n_in,
                              void* d_out, int out_size) {
    const float* output = (const float*)d_in[0];   // [4,8,256,256] fp32
    const int*   target = (const int*)d_in[1];     // [4,256,256] int32
    float*       out    = (float*)d_out;           // scalar

    k_init   <<<1, 32>>>();
    k_rowpass<<<BB*HH, WW>>>(target);
    k_colpass<<<BB*CC*(WW/JT), 256>>>();
    k_reduce <<<(BB*HH*WW)/(4*128), 128>>>(output);
    k_final  <<<1, 512>>>(out);
}